// round 4
// baseline (speedup 1.0000x reference)
#include <cuda_runtime.h>
#include <cuda_bf16.h>

// Problem constants
#define M_ROWS   8192          // B*S
#define HID      2048
#define NQKV     6144
#define NHEADS   16
#define HEADD    128
#define BATCH    4
#define SEQ      2048

// Scratch (device globals: allocation-free rule)
__device__ float g_qkv[M_ROWS * NQKV];    // [8192, 6144]
__device__ float g_attn[M_ROWS * HID];    // [8192, 2048]

// ---------------------------------------------------------------------------
// Packed f32x2 helpers (Blackwell sm_103a)
// ---------------------------------------------------------------------------
__device__ __forceinline__ unsigned long long pack_dup_f32(float x) {
    unsigned long long r;
    unsigned int u = __float_as_uint(x);
    asm("mov.b64 %0, {%1, %1};" : "=l"(r) : "r"(u));
    return r;
}
__device__ __forceinline__ void fma_f32x2(unsigned long long& d,
                                          unsigned long long a,
                                          unsigned long long b) {
    asm("fma.rn.f32x2 %0, %1, %2, %0;" : "+l"(d) : "l"(a), "l"(b));
}

// ---------------------------------------------------------------------------
// GEMM: C[M,N] = A[M,K] @ Bt[N,K]^T + bias[N]
// 128x128 tile, BK=16, 256 threads, 8x8 per thread, packed f32x2 FMA.
// M,N multiples of 128; K multiple of 16.
// ---------------------------------------------------------------------------
__global__ __launch_bounds__(256, 2)
void gemm_abt_f32x2(const float* __restrict__ A,
                    const float* __restrict__ Bt,
                    const float* __restrict__ bias,
                    float* __restrict__ C,
                    int M, int N, int K)
{
    __shared__ __align__(16) float As[16 * 128]; // [k][m]
    __shared__ __align__(16) float Bs[16 * 128]; // [k][n]

    const int tid = threadIdx.x;
    const int m0 = blockIdx.y * 128;
    const int n0 = blockIdx.x * 128;
    const int tr = tid >> 4;   // 0..15 -> rows tr*8..tr*8+7
    const int tc = tid & 15;   // 0..15 -> cols tc*8..tc*8+7

    // accumulators: 8 rows x 4 column-pairs (each pair = 2 fp32 packed)
    unsigned long long acc2[8][4];
#pragma unroll
    for (int i = 0; i < 8; i++)
#pragma unroll
        for (int j = 0; j < 4; j++) acc2[i][j] = 0ull;  // {+0.f,+0.f}

    for (int k0 = 0; k0 < K; k0 += 16) {
        // --- load A tile (128x16) ---
#pragma unroll
        for (int t = 0; t < 2; t++) {
            int v   = tid + t * 256;       // 0..511 float4 vectors
            int row = v >> 2;
            int kc  = (v & 3) << 2;
            float4 f = *(const float4*)(A + (size_t)(m0 + row) * K + k0 + kc);
            As[(kc + 0) * 128 + row] = f.x;
            As[(kc + 1) * 128 + row] = f.y;
            As[(kc + 2) * 128 + row] = f.z;
            As[(kc + 3) * 128 + row] = f.w;
        }
        // --- load B tile (128x16) ---
#pragma unroll
        for (int t = 0; t < 2; t++) {
            int v   = tid + t * 256;
            int row = v >> 2;
            int kc  = (v & 3) << 2;
            float4 f = *(const float4*)(Bt + (size_t)(n0 + row) * K + k0 + kc);
            Bs[(kc + 0) * 128 + row] = f.x;
            Bs[(kc + 1) * 128 + row] = f.y;
            Bs[(kc + 2) * 128 + row] = f.z;
            Bs[(kc + 3) * 128 + row] = f.w;
        }
        __syncthreads();

#pragma unroll
        for (int kk = 0; kk < 16; kk++) {
            float4 a0 = *(const float4*)&As[kk * 128 + tr * 8];
            float4 a1 = *(const float4*)&As[kk * 128 + tr * 8 + 4];
            ulonglong2 b0 = *(const ulonglong2*)&Bs[kk * 128 + tc * 8];
            ulonglong2 b1 = *(const ulonglong2*)&Bs[kk * 128 + tc * 8 + 4];
            unsigned long long bn[4] = {b0.x, b0.y, b1.x, b1.y};
            float am[8] = {a0.x, a0.y, a0.z, a0.w, a1.x, a1.y, a1.z, a1.w};
#pragma unroll
            for (int i = 0; i < 8; i++) {
                unsigned long long ad = pack_dup_f32(am[i]);
#pragma unroll
                for (int j = 0; j < 4; j++) fma_f32x2(acc2[i][j], ad, bn[j]);
            }
        }
        __syncthreads();
    }

    // epilogue: unpack, add bias, store
#pragma unroll
    for (int i = 0; i < 8; i++) {
        float* crow = C + (size_t)(m0 + tr * 8 + i) * N + n0 + tc * 8;
#pragma unroll
        for (int j = 0; j < 4; j++) {
            unsigned long long v = acc2[i][j];
            float lo = __uint_as_float((unsigned int)(v & 0xffffffffull));
            float hi = __uint_as_float((unsigned int)(v >> 32));
            float2 bb = *(const float2*)(bias + n0 + tc * 8 + 2 * j);
            float2 o;
            o.x = lo + bb.x;
            o.y = hi + bb.y;
            *(float2*)(crow + 2 * j) = o;
        }
    }
}

// ---------------------------------------------------------------------------
// Flash attention (fp32, causal). One CTA per (q-tile of 64, batch*head).
// BQ=64, BK=64, D=128, 256 threads = 8 warps; warp w owns q-rows w*8..w*8+7.
// Within a warp: lane computes score cols {lane, lane+32}; for PV/O, lane owns
// d = lane*4..lane*4+3 of all 8 rows.
// ---------------------------------------------------------------------------
#define ATTN_SMEM_FLOATS (64*128 + 64*129 + 64*128 + 64*64)
#define ATTN_SMEM_BYTES  (ATTN_SMEM_FLOATS * 4)

__global__ __launch_bounds__(256)
void attn_fa_kernel(const float* __restrict__ qkv, float* __restrict__ out)
{
    const int qt = blockIdx.x;       // 0..31
    const int bh = blockIdx.y;       // 0..63
    const int b  = bh >> 4;
    const int h  = bh & 15;
    const int q0 = qt * 64;

    const int tid  = threadIdx.x;
    const int lane = tid & 31;
    const int warp = tid >> 5;
    const int r0   = warp * 8;       // warp's first q-row within tile

    extern __shared__ float sm[];
    float* Qs = sm;                        // [64][128]
    float* Ks = Qs + 64 * 128;             // [64][129] (pad for conflict-free col reads)
    float* Vs = Ks + 64 * 129;             // [64][128]
    float* Ss = Vs + 64 * 128;             // [64][64]

    const float scale = 0.088388347648318447f;  // 1/sqrt(128)
    const float* base = qkv + (size_t)(b * SEQ) * NQKV + h * HEADD;

    // load Q tile (pre-scaled)
    {
        int r = tid >> 2;
        int c = (tid & 3) * 32;
#pragma unroll
        for (int j = 0; j < 8; j++) {
            float4 f = *(const float4*)(base + (size_t)(q0 + r) * NQKV + c + j * 4);
            f.x *= scale; f.y *= scale; f.z *= scale; f.w *= scale;
            *(float4*)&Qs[r * 128 + c + j * 4] = f;
        }
    }

    float O[8][4];
    float mrow[8], lrow[8];
#pragma unroll
    for (int i = 0; i < 8; i++) {
        O[i][0] = O[i][1] = O[i][2] = O[i][3] = 0.f;
        mrow[i] = -1e30f;
        lrow[i] = 0.f;
    }

    for (int kt = 0; kt <= qt; kt++) {
        const int k0 = kt * 64;
        __syncthreads();   // previous PV finished reading Ks/Vs
        // load K (stride 129) and V (stride 128)
        {
            int r = tid >> 2;
            int c = (tid & 3) * 32;
            const float* kp = base + 2048 + (size_t)(k0 + r) * NQKV + c;
            const float* vp = base + 4096 + (size_t)(k0 + r) * NQKV + c;
#pragma unroll
            for (int j = 0; j < 8; j++) {
                float4 f = *(const float4*)(kp + j * 4);
                Ks[r * 129 + c + j * 4 + 0] = f.x;
                Ks[r * 129 + c + j * 4 + 1] = f.y;
                Ks[r * 129 + c + j * 4 + 2] = f.z;
                Ks[r * 129 + c + j * 4 + 3] = f.w;
                float4 g = *(const float4*)(vp + j * 4);
                *(float4*)&Vs[r * 128 + c + j * 4] = g;
            }
        }
        __syncthreads();

        // S = Q K^T (scaled): acc[i][0] = col lane, acc[i][1] = col lane+32
        float acc[8][2];
#pragma unroll
        for (int i = 0; i < 8; i++) acc[i][0] = acc[i][1] = 0.f;

#pragma unroll 4
        for (int d = 0; d < 128; d++) {
            float kv0 = Ks[lane * 129 + d];
            float kv1 = Ks[(lane + 32) * 129 + d];
#pragma unroll
            for (int i = 0; i < 8; i++) {
                float qv = Qs[(r0 + i) * 128 + d];
                acc[i][0] = fmaf(qv, kv0, acc[i][0]);
                acc[i][1] = fmaf(qv, kv1, acc[i][1]);
            }
        }

        // causal mask (only diagonal tile; k0 == q0 there, so compare in-tile)
        if (kt == qt) {
#pragma unroll
            for (int i = 0; i < 8; i++) {
                int qr = r0 + i;
                if (lane > qr)      acc[i][0] = -1e30f;
                if (lane + 32 > qr) acc[i][1] = -1e30f;
            }
        }

        // online softmax update
#pragma unroll
        for (int i = 0; i < 8; i++) {
            float t = fmaxf(acc[i][0], acc[i][1]);
#pragma unroll
            for (int off = 16; off > 0; off >>= 1)
                t = fmaxf(t, __shfl_xor_sync(0xffffffffu, t, off));
            float mn = fmaxf(mrow[i], t);
            float p0 = __expf(acc[i][0] - mn);
            float p1 = __expf(acc[i][1] - mn);
            float s  = p0 + p1;
#pragma unroll
            for (int off = 16; off > 0; off >>= 1)
                s += __shfl_xor_sync(0xffffffffu, s, off);
            float a = __expf(mrow[i] - mn);
            lrow[i] = lrow[i] * a + s;
            mrow[i] = mn;
            O[i][0] *= a; O[i][1] *= a; O[i][2] *= a; O[i][3] *= a;
            Ss[(r0 + i) * 64 + lane]      = p0;
            Ss[(r0 + i) * 64 + lane + 32] = p1;
        }
        __syncwarp();   // warp-private rows of Ss

        // O += P @ V  (lane owns d = lane*4..lane*4+3)
#pragma unroll 2
        for (int c = 0; c < 64; c++) {
            float4 v = *(const float4*)&Vs[c * 128 + lane * 4];
#pragma unroll
            for (int i = 0; i < 8; i++) {
                float p = Ss[(r0 + i) * 64 + c];
                O[i][0] = fmaf(p, v.x, O[i][0]);
                O[i][1] = fmaf(p, v.y, O[i][1]);
                O[i][2] = fmaf(p, v.z, O[i][2]);
                O[i][3] = fmaf(p, v.w, O[i][3]);
            }
        }
    }

    // write attn output: [B*S, H*D]
#pragma unroll
    for (int i = 0; i < 8; i++) {
        float inv = 1.0f / lrow[i];
        float4 o;
        o.x = O[i][0] * inv;
        o.y = O[i][1] * inv;
        o.z = O[i][2] * inv;
        o.w = O[i][3] * inv;
        size_t row = (size_t)(b * SEQ + q0 + r0 + i);
        *(float4*)&out[row * HID + h * HEADD + lane * 4] = o;
    }
}

// ---------------------------------------------------------------------------
// Launch: QKV GEMM -> flash attention -> dense GEMM
// ---------------------------------------------------------------------------
extern "C" void kernel_launch(void* const* d_in, const int* in_sizes, int n_in,
                              void* d_out, int out_size)
{
    (void)in_sizes; (void)n_in; (void)out_size;
    const float* hs   = (const float*)d_in[0];
    const float* wqkv = (const float*)d_in[1];
    const float* bqkv = (const float*)d_in[2];
    const float* wd   = (const float*)d_in[3];
    const float* bd   = (const float*)d_in[4];
    float* out = (float*)d_out;

    float *qkv = nullptr, *attn = nullptr;
    cudaGetSymbolAddress((void**)&qkv,  g_qkv);
    cudaGetSymbolAddress((void**)&attn, g_attn);

    cudaFuncSetAttribute(attn_fa_kernel,
                         cudaFuncAttributeMaxDynamicSharedMemorySize,
                         ATTN_SMEM_BYTES);

    // 1) qkv = hs @ w_qkv^T + b_qkv      [8192, 6144]
    {
        dim3 grid(NQKV / 128, M_ROWS / 128);
        gemm_abt_f32x2<<<grid, 256>>>(hs, wqkv, bqkv, qkv, M_ROWS, NQKV, HID);
    }
    // 2) causal flash attention          [8192, 2048]
    {
        dim3 grid(SEQ / 64, BATCH * NHEADS);
        attn_fa_kernel<<<grid, 256, ATTN_SMEM_BYTES>>>(qkv, attn);
    }
    // 3) out = attn @ w_dense^T + b_dense [8192, 2048]
    {
        dim3 grid(HID / 128, M_ROWS / 128);
        gemm_abt_f32x2<<<grid, 256>>>(attn, wd, bd, out, M_ROWS, HID, HID);
    }
}

// round 6
// speedup vs baseline: 1.8629x; 1.8629x over previous
#include <cuda_runtime.h>
#include <cuda_bf16.h>
#include <cstdint>

// Problem constants
#define M_ROWS   8192          // B*S
#define HID      2048
#define NQKV     6144
#define NHEADS   16
#define HEADD    128
#define BATCH    4
#define SEQ      2048

// Scratch (device globals: allocation-free rule)
__device__ float g_qkv[M_ROWS * NQKV];    // [8192, 6144]
__device__ float g_attn[M_ROWS * HID];    // [8192, 2048]

// ---------------------------------------------------------------------------
// tf32 helpers (portable PTX, sm_80+; no tcgen05 — harness targets sm_103)
// ---------------------------------------------------------------------------
__device__ __forceinline__ uint32_t cvt_tf32(float f) {
    uint32_t r;
    asm("cvt.rna.tf32.f32 %0, %1;" : "=r"(r) : "f"(f));
    return r;
}

__device__ __forceinline__ void mma_tf32(float& d0, float& d1, float& d2, float& d3,
                                         uint32_t a0, uint32_t a1, uint32_t a2, uint32_t a3,
                                         uint32_t b0, uint32_t b1) {
    asm volatile(
        "mma.sync.aligned.m16n8k8.row.col.f32.tf32.tf32.f32 "
        "{%0,%1,%2,%3}, {%4,%5,%6,%7}, {%8,%9}, {%0,%1,%2,%3};"
        : "+f"(d0), "+f"(d1), "+f"(d2), "+f"(d3)
        : "r"(a0), "r"(a1), "r"(a2), "r"(a3), "r"(b0), "r"(b1));
}

// ---------------------------------------------------------------------------
// tf32 tensor-core GEMM: C[M,N] = tf32(A[M,K]) @ tf32(Bt[N,K])^T + bias[N]
// CTA tile 128x128, BK=32, 256 threads = 8 warps (2x4), warp tile 64x32.
// SMEM rows padded to 36 floats -> fragment LDS bank = (4*gid+tig): conflict-free.
// Double-buffered SMEM, register prefetch of next global tile.
// M,N multiples of 128; K multiple of 32.
// ---------------------------------------------------------------------------
#define APITCH    36
#define ATILE_F   (128 * APITCH)                 // floats per tile (A or B)
#define GT_SMEM   (2 * 2 * ATILE_F * 4)          // 2 buffers x (A+B) = 73728 B

__global__ __launch_bounds__(256, 1)
void gemm_tf32_mma(const float* __restrict__ A,
                   const float* __restrict__ Bt,
                   const float* __restrict__ bias,
                   float* __restrict__ C,
                   int N, int K)
{
    extern __shared__ __align__(16) uint32_t smu[];

    const int tid  = threadIdx.x;
    const int lane = tid & 31;
    const int wid  = tid >> 5;
    const int gid  = lane >> 2;      // 0..7
    const int tig  = lane & 3;       // 0..3
    const int wm   = (wid >> 2) * 64;  // warp row offset in tile
    const int wn   = (wid & 3) * 32;   // warp col offset in tile
    const int m0 = blockIdx.y * 128;
    const int n0 = blockIdx.x * 128;

    // staging indices: thread t handles rows (v>>3), k-chunk (v&7)*4 for v=tid+256t
    int srow[4], sc4[4];
#pragma unroll
    for (int t = 0; t < 4; t++) {
        int v = tid + t * 256;
        srow[t] = v >> 3;
        sc4[t]  = (v & 7) * 4;
    }

    float acc[4][4][4];
#pragma unroll
    for (int mt = 0; mt < 4; mt++)
#pragma unroll
        for (int nt = 0; nt < 4; nt++)
#pragma unroll
            for (int c = 0; c < 4; c++) acc[mt][nt][c] = 0.f;

    const int niter = K >> 5;        // BK = 32
    float4 ra[4], rb[4];

    // prologue: load iter 0 into regs, store to buffer 0
#pragma unroll
    for (int t = 0; t < 4; t++) {
        ra[t] = *(const float4*)(A  + (size_t)(m0 + srow[t]) * K + sc4[t]);
        rb[t] = *(const float4*)(Bt + (size_t)(n0 + srow[t]) * K + sc4[t]);
    }
    {
        uint32_t* As = smu;
        uint32_t* Bs = smu + ATILE_F;
#pragma unroll
        for (int t = 0; t < 4; t++) {
            uint32_t* pa = As + srow[t] * APITCH + sc4[t];
            pa[0] = cvt_tf32(ra[t].x); pa[1] = cvt_tf32(ra[t].y);
            pa[2] = cvt_tf32(ra[t].z); pa[3] = cvt_tf32(ra[t].w);
            uint32_t* pb = Bs + srow[t] * APITCH + sc4[t];
            pb[0] = cvt_tf32(rb[t].x); pb[1] = cvt_tf32(rb[t].y);
            pb[2] = cvt_tf32(rb[t].z); pb[3] = cvt_tf32(rb[t].w);
        }
    }
    __syncthreads();

    for (int kt = 0; kt < niter; kt++) {
        const int buf = kt & 1;
        const uint32_t* As = smu + buf * (2 * ATILE_F);
        const uint32_t* Bs = As + ATILE_F;

        // prefetch next global tile into registers
        if (kt + 1 < niter) {
            const int k0 = (kt + 1) << 5;
#pragma unroll
            for (int t = 0; t < 4; t++) {
                ra[t] = *(const float4*)(A  + (size_t)(m0 + srow[t]) * K + k0 + sc4[t]);
                rb[t] = *(const float4*)(Bt + (size_t)(n0 + srow[t]) * K + k0 + sc4[t]);
            }
        }

        // compute: 4 k8-steps x (4 m-tiles x 4 n-tiles) MMAs
#pragma unroll
        for (int s = 0; s < 4; s++) {
            uint32_t af[4][4], bf[4][2];
#pragma unroll
            for (int mt = 0; mt < 4; mt++) {
                const uint32_t* p = As + (wm + mt * 16 + gid) * APITCH + s * 8 + tig;
                af[mt][0] = p[0];
                af[mt][1] = p[8 * APITCH];
                af[mt][2] = p[4];
                af[mt][3] = p[8 * APITCH + 4];
            }
#pragma unroll
            for (int nt = 0; nt < 4; nt++) {
                const uint32_t* p = Bs + (wn + nt * 8 + gid) * APITCH + s * 8 + tig;
                bf[nt][0] = p[0];
                bf[nt][1] = p[4];
            }
#pragma unroll
            for (int mt = 0; mt < 4; mt++)
#pragma unroll
                for (int nt = 0; nt < 4; nt++)
                    mma_tf32(acc[mt][nt][0], acc[mt][nt][1],
                             acc[mt][nt][2], acc[mt][nt][3],
                             af[mt][0], af[mt][1], af[mt][2], af[mt][3],
                             bf[nt][0], bf[nt][1]);
        }

        // store prefetched tile into the other buffer
        if (kt + 1 < niter) {
            uint32_t* Aw = smu + (buf ^ 1) * (2 * ATILE_F);
            uint32_t* Bw = Aw + ATILE_F;
#pragma unroll
            for (int t = 0; t < 4; t++) {
                uint32_t* pa = Aw + srow[t] * APITCH + sc4[t];
                pa[0] = cvt_tf32(ra[t].x); pa[1] = cvt_tf32(ra[t].y);
                pa[2] = cvt_tf32(ra[t].z); pa[3] = cvt_tf32(ra[t].w);
                uint32_t* pb = Bw + srow[t] * APITCH + sc4[t];
                pb[0] = cvt_tf32(rb[t].x); pb[1] = cvt_tf32(rb[t].y);
                pb[2] = cvt_tf32(rb[t].z); pb[3] = cvt_tf32(rb[t].w);
            }
            __syncthreads();
        }
    }

    // epilogue: C fragment (gid, 2*tig) rows, +bias, float2 stores
#pragma unroll
    for (int mt = 0; mt < 4; mt++) {
        const int r0 = m0 + wm + mt * 16 + gid;
#pragma unroll
        for (int nt = 0; nt < 4; nt++) {
            const int col = n0 + wn + nt * 8 + 2 * tig;
            float2 bb = *(const float2*)(bias + col);
            float2 o0, o1;
            o0.x = acc[mt][nt][0] + bb.x;
            o0.y = acc[mt][nt][1] + bb.y;
            o1.x = acc[mt][nt][2] + bb.x;
            o1.y = acc[mt][nt][3] + bb.y;
            *(float2*)(C + (size_t)r0 * N + col)       = o0;
            *(float2*)(C + (size_t)(r0 + 8) * N + col) = o1;
        }
    }
}

// ---------------------------------------------------------------------------
// Flash attention (fp32, causal) — unchanged from R4 passing baseline.
// One CTA per (q-tile of 64, batch*head). BQ=64, BK=64, D=128, 8 warps.
// ---------------------------------------------------------------------------
#define ATTN_SMEM_FLOATS (64*128 + 64*129 + 64*128 + 64*64)
#define ATTN_SMEM_BYTES  (ATTN_SMEM_FLOATS * 4)

__global__ __launch_bounds__(256)
void attn_fa_kernel(const float* __restrict__ qkv, float* __restrict__ out)
{
    const int qt = blockIdx.x;
    const int bh = blockIdx.y;
    const int b  = bh >> 4;
    const int h  = bh & 15;
    const int q0 = qt * 64;

    const int tid  = threadIdx.x;
    const int lane = tid & 31;
    const int warp = tid >> 5;
    const int r0   = warp * 8;

    extern __shared__ float smf[];
    float* Qs = smf;
    float* Ks = Qs + 64 * 128;
    float* Vs = Ks + 64 * 129;
    float* Ss = Vs + 64 * 128;

    const float scale = 0.088388347648318447f;
    const float* base = qkv + (size_t)(b * SEQ) * NQKV + h * HEADD;

    {
        int r = tid >> 2;
        int c = (tid & 3) * 32;
#pragma unroll
        for (int j = 0; j < 8; j++) {
            float4 f = *(const float4*)(base + (size_t)(q0 + r) * NQKV + c + j * 4);
            f.x *= scale; f.y *= scale; f.z *= scale; f.w *= scale;
            *(float4*)&Qs[r * 128 + c + j * 4] = f;
        }
    }

    float O[8][4];
    float mrow[8], lrow[8];
#pragma unroll
    for (int i = 0; i < 8; i++) {
        O[i][0] = O[i][1] = O[i][2] = O[i][3] = 0.f;
        mrow[i] = -1e30f;
        lrow[i] = 0.f;
    }

    for (int kt = 0; kt <= qt; kt++) {
        const int k0 = kt * 64;
        __syncthreads();
        {
            int r = tid >> 2;
            int c = (tid & 3) * 32;
            const float* kp = base + 2048 + (size_t)(k0 + r) * NQKV + c;
            const float* vp = base + 4096 + (size_t)(k0 + r) * NQKV + c;
#pragma unroll
            for (int j = 0; j < 8; j++) {
                float4 f = *(const float4*)(kp + j * 4);
                Ks[r * 129 + c + j * 4 + 0] = f.x;
                Ks[r * 129 + c + j * 4 + 1] = f.y;
                Ks[r * 129 + c + j * 4 + 2] = f.z;
                Ks[r * 129 + c + j * 4 + 3] = f.w;
                float4 g = *(const float4*)(vp + j * 4);
                *(float4*)&Vs[r * 128 + c + j * 4] = g;
            }
        }
        __syncthreads();

        float acc[8][2];
#pragma unroll
        for (int i = 0; i < 8; i++) acc[i][0] = acc[i][1] = 0.f;

#pragma unroll 4
        for (int d = 0; d < 128; d++) {
            float kv0 = Ks[lane * 129 + d];
            float kv1 = Ks[(lane + 32) * 129 + d];
#pragma unroll
            for (int i = 0; i < 8; i++) {
                float qv = Qs[(r0 + i) * 128 + d];
                acc[i][0] = fmaf(qv, kv0, acc[i][0]);
                acc[i][1] = fmaf(qv, kv1, acc[i][1]);
            }
        }

        if (kt == qt) {
#pragma unroll
            for (int i = 0; i < 8; i++) {
                int qr = r0 + i;
                if (lane > qr)      acc[i][0] = -1e30f;
                if (lane + 32 > qr) acc[i][1] = -1e30f;
            }
        }

#pragma unroll
        for (int i = 0; i < 8; i++) {
            float t = fmaxf(acc[i][0], acc[i][1]);
#pragma unroll
            for (int off = 16; off > 0; off >>= 1)
                t = fmaxf(t, __shfl_xor_sync(0xffffffffu, t, off));
            float mn = fmaxf(mrow[i], t);
            float p0 = __expf(acc[i][0] - mn);
            float p1 = __expf(acc[i][1] - mn);
            float s  = p0 + p1;
#pragma unroll
            for (int off = 16; off > 0; off >>= 1)
                s += __shfl_xor_sync(0xffffffffu, s, off);
            float a = __expf(mrow[i] - mn);
            lrow[i] = lrow[i] * a + s;
            mrow[i] = mn;
            O[i][0] *= a; O[i][1] *= a; O[i][2] *= a; O[i][3] *= a;
            Ss[(r0 + i) * 64 + lane]      = p0;
            Ss[(r0 + i) * 64 + lane + 32] = p1;
        }
        __syncwarp();

#pragma unroll 2
        for (int c = 0; c < 64; c++) {
            float4 v = *(const float4*)&Vs[c * 128 + lane * 4];
#pragma unroll
            for (int i = 0; i < 8; i++) {
                float p = Ss[(r0 + i) * 64 + c];
                O[i][0] = fmaf(p, v.x, O[i][0]);
                O[i][1] = fmaf(p, v.y, O[i][1]);
                O[i][2] = fmaf(p, v.z, O[i][2]);
                O[i][3] = fmaf(p, v.w, O[i][3]);
            }
        }
    }

#pragma unroll
    for (int i = 0; i < 8; i++) {
        float inv = 1.0f / lrow[i];
        float4 o;
        o.x = O[i][0] * inv;
        o.y = O[i][1] * inv;
        o.z = O[i][2] * inv;
        o.w = O[i][3] * inv;
        size_t row = (size_t)(b * SEQ + q0 + r0 + i);
        *(float4*)&out[row * HID + h * HEADD + lane * 4] = o;
    }
}

// ---------------------------------------------------------------------------
// Launch: QKV GEMM (mma.sync tf32) -> flash attention -> dense GEMM
// ---------------------------------------------------------------------------
extern "C" void kernel_launch(void* const* d_in, const int* in_sizes, int n_in,
                              void* d_out, int out_size)
{
    (void)in_sizes; (void)n_in; (void)out_size;
    const float* hs   = (const float*)d_in[0];
    const float* wqkv = (const float*)d_in[1];
    const float* bqkv = (const float*)d_in[2];
    const float* wd   = (const float*)d_in[3];
    const float* bd   = (const float*)d_in[4];
    float* out = (float*)d_out;

    float *qkv = nullptr, *attn = nullptr;
    cudaGetSymbolAddress((void**)&qkv,  g_qkv);
    cudaGetSymbolAddress((void**)&attn, g_attn);

    cudaFuncSetAttribute(gemm_tf32_mma,
                         cudaFuncAttributeMaxDynamicSharedMemorySize, GT_SMEM);
    cudaFuncSetAttribute(attn_fa_kernel,
                         cudaFuncAttributeMaxDynamicSharedMemorySize,
                         ATTN_SMEM_BYTES);

    // 1) qkv = hs @ w_qkv^T + b_qkv      [8192, 6144]
    {
        dim3 grid(NQKV / 128, M_ROWS / 128);
        gemm_tf32_mma<<<grid, 256, GT_SMEM>>>(hs, wqkv, bqkv, qkv, NQKV, HID);
    }
    // 2) causal flash attention          [8192, 2048]
    {
        dim3 grid(SEQ / 64, BATCH * NHEADS);
        attn_fa_kernel<<<grid, 256, ATTN_SMEM_BYTES>>>(qkv, attn);
    }
    // 3) out = attn @ w_dense^T + b_dense [8192, 2048]
    {
        dim3 grid(HID / 128, M_ROWS / 128);
        gemm_tf32_mma<<<grid, 256, GT_SMEM>>>(attn, wd, bd, out, HID, HID);
    }
}

// round 7
// speedup vs baseline: 3.1282x; 1.6792x over previous
#include <cuda_runtime.h>
#include <cuda_bf16.h>
#include <cstdint>

// Problem constants
#define M_ROWS   8192          // B*S
#define HID      2048
#define NQKV     6144
#define NHEADS   16
#define HEADD    128
#define BATCH    4
#define SEQ      2048

// Scratch (device globals: allocation-free rule)
__device__ float g_qkv[M_ROWS * NQKV];    // [8192, 6144]
__device__ float g_attn[M_ROWS * HID];    // [8192, 2048]

// ---------------------------------------------------------------------------
// tf32 helpers (portable PTX, sm_80+; no tcgen05 — harness targets sm_103)
// ---------------------------------------------------------------------------
__device__ __forceinline__ uint32_t cvt_tf32(float f) {
    uint32_t r;
    asm("cvt.rna.tf32.f32 %0, %1;" : "=r"(r) : "f"(f));
    return r;
}

__device__ __forceinline__ void mma_tf32(float& d0, float& d1, float& d2, float& d3,
                                         uint32_t a0, uint32_t a1, uint32_t a2, uint32_t a3,
                                         uint32_t b0, uint32_t b1) {
    asm volatile(
        "mma.sync.aligned.m16n8k8.row.col.f32.tf32.tf32.f32 "
        "{%0,%1,%2,%3}, {%4,%5,%6,%7}, {%8,%9}, {%0,%1,%2,%3};"
        : "+f"(d0), "+f"(d1), "+f"(d2), "+f"(d3)
        : "r"(a0), "r"(a1), "r"(a2), "r"(a3), "r"(b0), "r"(b1));
}

// ---------------------------------------------------------------------------
// tf32 tensor-core GEMM: C[M,N] = tf32(A[M,K]) @ tf32(Bt[N,K])^T + bias[N]
// (unchanged from R6 passing version)
// ---------------------------------------------------------------------------
#define APITCH    36
#define ATILE_F   (128 * APITCH)
#define GT_SMEM   (2 * 2 * ATILE_F * 4)

__global__ __launch_bounds__(256, 1)
void gemm_tf32_mma(const float* __restrict__ A,
                   const float* __restrict__ Bt,
                   const float* __restrict__ bias,
                   float* __restrict__ C,
                   int N, int K)
{
    extern __shared__ __align__(16) uint32_t smu[];

    const int tid  = threadIdx.x;
    const int lane = tid & 31;
    const int wid  = tid >> 5;
    const int gid  = lane >> 2;
    const int tig  = lane & 3;
    const int wm   = (wid >> 2) * 64;
    const int wn   = (wid & 3) * 32;
    const int m0 = blockIdx.y * 128;
    const int n0 = blockIdx.x * 128;

    int srow[4], sc4[4];
#pragma unroll
    for (int t = 0; t < 4; t++) {
        int v = tid + t * 256;
        srow[t] = v >> 3;
        sc4[t]  = (v & 7) * 4;
    }

    float acc[4][4][4];
#pragma unroll
    for (int mt = 0; mt < 4; mt++)
#pragma unroll
        for (int nt = 0; nt < 4; nt++)
#pragma unroll
            for (int c = 0; c < 4; c++) acc[mt][nt][c] = 0.f;

    const int niter = K >> 5;
    float4 ra[4], rb[4];

#pragma unroll
    for (int t = 0; t < 4; t++) {
        ra[t] = *(const float4*)(A  + (size_t)(m0 + srow[t]) * K + sc4[t]);
        rb[t] = *(const float4*)(Bt + (size_t)(n0 + srow[t]) * K + sc4[t]);
    }
    {
        uint32_t* As = smu;
        uint32_t* Bs = smu + ATILE_F;
#pragma unroll
        for (int t = 0; t < 4; t++) {
            uint32_t* pa = As + srow[t] * APITCH + sc4[t];
            pa[0] = cvt_tf32(ra[t].x); pa[1] = cvt_tf32(ra[t].y);
            pa[2] = cvt_tf32(ra[t].z); pa[3] = cvt_tf32(ra[t].w);
            uint32_t* pb = Bs + srow[t] * APITCH + sc4[t];
            pb[0] = cvt_tf32(rb[t].x); pb[1] = cvt_tf32(rb[t].y);
            pb[2] = cvt_tf32(rb[t].z); pb[3] = cvt_tf32(rb[t].w);
        }
    }
    __syncthreads();

    for (int kt = 0; kt < niter; kt++) {
        const int buf = kt & 1;
        const uint32_t* As = smu + buf * (2 * ATILE_F);
        const uint32_t* Bs = As + ATILE_F;

        if (kt + 1 < niter) {
            const int k0 = (kt + 1) << 5;
#pragma unroll
            for (int t = 0; t < 4; t++) {
                ra[t] = *(const float4*)(A  + (size_t)(m0 + srow[t]) * K + k0 + sc4[t]);
                rb[t] = *(const float4*)(Bt + (size_t)(n0 + srow[t]) * K + k0 + sc4[t]);
            }
        }

#pragma unroll
        for (int s = 0; s < 4; s++) {
            uint32_t af[4][4], bf[4][2];
#pragma unroll
            for (int mt = 0; mt < 4; mt++) {
                const uint32_t* p = As + (wm + mt * 16 + gid) * APITCH + s * 8 + tig;
                af[mt][0] = p[0];
                af[mt][1] = p[8 * APITCH];
                af[mt][2] = p[4];
                af[mt][3] = p[8 * APITCH + 4];
            }
#pragma unroll
            for (int nt = 0; nt < 4; nt++) {
                const uint32_t* p = Bs + (wn + nt * 8 + gid) * APITCH + s * 8 + tig;
                bf[nt][0] = p[0];
                bf[nt][1] = p[4];
            }
#pragma unroll
            for (int mt = 0; mt < 4; mt++)
#pragma unroll
                for (int nt = 0; nt < 4; nt++)
                    mma_tf32(acc[mt][nt][0], acc[mt][nt][1],
                             acc[mt][nt][2], acc[mt][nt][3],
                             af[mt][0], af[mt][1], af[mt][2], af[mt][3],
                             bf[nt][0], bf[nt][1]);
        }

        if (kt + 1 < niter) {
            uint32_t* Aw = smu + (buf ^ 1) * (2 * ATILE_F);
            uint32_t* Bw = Aw + ATILE_F;
#pragma unroll
            for (int t = 0; t < 4; t++) {
                uint32_t* pa = Aw + srow[t] * APITCH + sc4[t];
                pa[0] = cvt_tf32(ra[t].x); pa[1] = cvt_tf32(ra[t].y);
                pa[2] = cvt_tf32(ra[t].z); pa[3] = cvt_tf32(ra[t].w);
                uint32_t* pb = Bw + srow[t] * APITCH + sc4[t];
                pb[0] = cvt_tf32(rb[t].x); pb[1] = cvt_tf32(rb[t].y);
                pb[2] = cvt_tf32(rb[t].z); pb[3] = cvt_tf32(rb[t].w);
            }
            __syncthreads();
        }
    }

#pragma unroll
    for (int mt = 0; mt < 4; mt++) {
        const int r0 = m0 + wm + mt * 16 + gid;
#pragma unroll
        for (int nt = 0; nt < 4; nt++) {
            const int col = n0 + wn + nt * 8 + 2 * tig;
            float2 bb = *(const float2*)(bias + col);
            float2 o0, o1;
            o0.x = acc[mt][nt][0] + bb.x;
            o0.y = acc[mt][nt][1] + bb.y;
            o1.x = acc[mt][nt][2] + bb.x;
            o1.y = acc[mt][nt][3] + bb.y;
            *(float2*)(C + (size_t)r0 * N + col)       = o0;
            *(float2*)(C + (size_t)(r0 + 8) * N + col) = o1;
        }
    }
}

// ---------------------------------------------------------------------------
// Tensor-core flash attention (tf32 mma, causal).
// BQ=128, BK=64, D=128. 256 threads = 8 warps; warp w owns q-rows w*16..+15
// and the FULL 64 k-cols (softmax reductions stay in a 4-lane shfl group).
// QK^T: A=Q [16,128] frags from Qs; B=K rows (K-major == mma col-major B).
// PV:   A=P [16,64] frags from Ps; B=V^T stored as Vt[d][kv] (pitch 68 ->
//       fragment bank = 4*gid+tig, conflict-free). O accumulates fp32 regs.
// ---------------------------------------------------------------------------
#define AT_QP 132
#define AT_KP 132
#define AT_VP 68
#define AT_PP 68
#define AT_SMEM_F (128*AT_QP + 64*AT_KP + 128*AT_VP + 128*AT_PP)
#define AT_SMEM_B (AT_SMEM_F * 4)     // 171008 bytes

__global__ __launch_bounds__(256, 1)
void attn_mma_kernel(const float* __restrict__ qkv, float* __restrict__ out)
{
    const int qt = blockIdx.x;       // 0..15 (q-tiles of 128)
    const int bh = blockIdx.y;       // 0..63
    const int b  = bh >> 4;
    const int h  = bh & 15;
    const int q0 = qt * 128;

    const int tid  = threadIdx.x;
    const int lane = tid & 31;
    const int warp = tid >> 5;
    const int gid  = lane >> 2;      // 0..7
    const int tig  = lane & 3;       // 0..3
    const int wm   = warp * 16;      // warp's q-row offset in tile

    extern __shared__ __align__(16) uint32_t asm_[];
    uint32_t* Qs = asm_;                       // [128][132] tf32 bits
    uint32_t* Ks = Qs + 128 * AT_QP;           // [64][132]
    uint32_t* Vt = Ks + 64 * AT_KP;            // [128 d][68 kv]
    uint32_t* Ps = Vt + 128 * AT_VP;           // [128][68]

    const float scale = 0.088388347648318447f;  // 1/sqrt(128)
    const float* base = qkv + (size_t)(b * SEQ) * NQKV + h * HEADD;

    // ---- load Q tile (scaled, tf32) ----
    {
        int r  = tid >> 1;
        int c0 = (tid & 1) * 64;
        const float* qp = base + (size_t)(q0 + r) * NQKV + c0;
        uint32_t* dst = Qs + r * AT_QP + c0;
#pragma unroll
        for (int j = 0; j < 16; j++) {
            float4 f = *(const float4*)(qp + j * 4);
            dst[j*4+0] = cvt_tf32(f.x * scale);
            dst[j*4+1] = cvt_tf32(f.y * scale);
            dst[j*4+2] = cvt_tf32(f.z * scale);
            dst[j*4+3] = cvt_tf32(f.w * scale);
        }
    }

    float O[16][4];
#pragma unroll
    for (int nt = 0; nt < 16; nt++)
#pragma unroll
        for (int c = 0; c < 4; c++) O[nt][c] = 0.f;
    float m0r = -1e30f, m1r = -1e30f;
    float l0r = 0.f,    l1r = 0.f;

    const int rA = q0 + wm + gid;       // this thread's first q-row (global seq)
    const int rB = rA + 8;
    const int niter = qt * 2 + 2;

    for (int kt = 0; kt < niter; kt++) {
        const int k0 = kt * 64;
        __syncthreads();   // previous iteration done reading Ks/Vt
        // ---- load K (tf32) and V transposed (tf32) ----
        {
            int r  = tid >> 2;
            int c0 = (tid & 3) * 32;
            const float* kp = base + 2048 + (size_t)(k0 + r) * NQKV + c0;
            const float* vp = base + 4096 + (size_t)(k0 + r) * NQKV + c0;
            uint32_t* kdst = Ks + r * AT_KP + c0;
#pragma unroll
            for (int j = 0; j < 8; j++) {
                float4 f = *(const float4*)(kp + j * 4);
                kdst[j*4+0] = cvt_tf32(f.x);
                kdst[j*4+1] = cvt_tf32(f.y);
                kdst[j*4+2] = cvt_tf32(f.z);
                kdst[j*4+3] = cvt_tf32(f.w);
                float4 g = *(const float4*)(vp + j * 4);
                Vt[(c0 + j*4 + 0) * AT_VP + r] = cvt_tf32(g.x);
                Vt[(c0 + j*4 + 1) * AT_VP + r] = cvt_tf32(g.y);
                Vt[(c0 + j*4 + 2) * AT_VP + r] = cvt_tf32(g.z);
                Vt[(c0 + j*4 + 3) * AT_VP + r] = cvt_tf32(g.w);
            }
        }
        __syncthreads();

        // ---- S = Q K^T : warp computes 16 rows x 64 cols ----
        float acc[8][4];
#pragma unroll
        for (int nt = 0; nt < 8; nt++)
#pragma unroll
            for (int c = 0; c < 4; c++) acc[nt][c] = 0.f;

#pragma unroll
        for (int s = 0; s < 16; s++) {
            const uint32_t* pa = Qs + (wm + gid) * AT_QP + s * 8 + tig;
            uint32_t a0 = pa[0];
            uint32_t a1 = pa[8 * AT_QP];
            uint32_t a2 = pa[4];
            uint32_t a3 = pa[8 * AT_QP + 4];
#pragma unroll
            for (int nt = 0; nt < 8; nt++) {
                const uint32_t* pb = Ks + (nt * 8 + gid) * AT_KP + s * 8 + tig;
                mma_tf32(acc[nt][0], acc[nt][1], acc[nt][2], acc[nt][3],
                         a0, a1, a2, a3, pb[0], pb[4]);
            }
        }

        // ---- causal mask (only the last two k-tiles can cross the diagonal) ----
        if (kt >= niter - 2) {
#pragma unroll
            for (int nt = 0; nt < 8; nt++) {
                int c0c = k0 + nt * 8 + 2 * tig;
                if (c0c > rA)     acc[nt][0] = -1e30f;
                if (c0c + 1 > rA) acc[nt][1] = -1e30f;
                if (c0c > rB)     acc[nt][2] = -1e30f;
                if (c0c + 1 > rB) acc[nt][3] = -1e30f;
            }
        }

        // ---- online softmax (4-lane groups share a row) ----
        float mx0 = -1e30f, mx1 = -1e30f;
#pragma unroll
        for (int nt = 0; nt < 8; nt++) {
            mx0 = fmaxf(mx0, fmaxf(acc[nt][0], acc[nt][1]));
            mx1 = fmaxf(mx1, fmaxf(acc[nt][2], acc[nt][3]));
        }
        mx0 = fmaxf(mx0, __shfl_xor_sync(0xffffffffu, mx0, 1));
        mx0 = fmaxf(mx0, __shfl_xor_sync(0xffffffffu, mx0, 2));
        mx1 = fmaxf(mx1, __shfl_xor_sync(0xffffffffu, mx1, 1));
        mx1 = fmaxf(mx1, __shfl_xor_sync(0xffffffffu, mx1, 2));

        float mn0 = fmaxf(m0r, mx0);
        float mn1 = fmaxf(m1r, mx1);
        float al0 = __expf(m0r - mn0);
        float al1 = __expf(m1r - mn1);

        float s0 = 0.f, s1 = 0.f;
        uint32_t* prowA = Ps + (wm + gid) * AT_PP + 2 * tig;
        uint32_t* prowB = prowA + 8 * AT_PP;
#pragma unroll
        for (int nt = 0; nt < 8; nt++) {
            float p00 = __expf(acc[nt][0] - mn0);
            float p01 = __expf(acc[nt][1] - mn0);
            float p10 = __expf(acc[nt][2] - mn1);
            float p11 = __expf(acc[nt][3] - mn1);
            s0 += p00 + p01;
            s1 += p10 + p11;
            uint2 wa = make_uint2(cvt_tf32(p00), cvt_tf32(p01));
            uint2 wb = make_uint2(cvt_tf32(p10), cvt_tf32(p11));
            *(uint2*)(prowA + nt * 8) = wa;
            *(uint2*)(prowB + nt * 8) = wb;
        }
        s0 += __shfl_xor_sync(0xffffffffu, s0, 1);
        s0 += __shfl_xor_sync(0xffffffffu, s0, 2);
        s1 += __shfl_xor_sync(0xffffffffu, s1, 1);
        s1 += __shfl_xor_sync(0xffffffffu, s1, 2);

        l0r = l0r * al0 + s0;  m0r = mn0;
        l1r = l1r * al1 + s1;  m1r = mn1;

#pragma unroll
        for (int nt = 0; nt < 16; nt++) {
            O[nt][0] *= al0;  O[nt][1] *= al0;
            O[nt][2] *= al1;  O[nt][3] *= al1;
        }
        __syncwarp();   // Ps rows are warp-private; order stores before frag loads

        // ---- O += P V : warp computes 16 rows x 128 d ----
#pragma unroll
        for (int s = 0; s < 8; s++) {
            const uint32_t* pa = Ps + (wm + gid) * AT_PP + s * 8 + tig;
            uint32_t a0 = pa[0];
            uint32_t a1 = pa[8 * AT_PP];
            uint32_t a2 = pa[4];
            uint32_t a3 = pa[8 * AT_PP + 4];
#pragma unroll
            for (int nt = 0; nt < 16; nt++) {
                const uint32_t* pb = Vt + (nt * 8 + gid) * AT_VP + s * 8 + tig;
                mma_tf32(O[nt][0], O[nt][1], O[nt][2], O[nt][3],
                         a0, a1, a2, a3, pb[0], pb[4]);
            }
        }
    }

    // ---- epilogue: normalize, write [B*S, H*D] ----
    const float inv0 = 1.0f / l0r;
    const float inv1 = 1.0f / l1r;
    float* outA = out + (size_t)(b * SEQ + rA) * HID + h * HEADD + 2 * tig;
    float* outB = out + (size_t)(b * SEQ + rB) * HID + h * HEADD + 2 * tig;
#pragma unroll
    for (int nt = 0; nt < 16; nt++) {
        float2 oa, ob;
        oa.x = O[nt][0] * inv0;  oa.y = O[nt][1] * inv0;
        ob.x = O[nt][2] * inv1;  ob.y = O[nt][3] * inv1;
        *(float2*)(outA + nt * 8) = oa;
        *(float2*)(outB + nt * 8) = ob;
    }
}

// ---------------------------------------------------------------------------
// Launch: QKV GEMM (mma tf32) -> flash attention (mma tf32) -> dense GEMM
// ---------------------------------------------------------------------------
extern "C" void kernel_launch(void* const* d_in, const int* in_sizes, int n_in,
                              void* d_out, int out_size)
{
    (void)in_sizes; (void)n_in; (void)out_size;
    const float* hs   = (const float*)d_in[0];
    const float* wqkv = (const float*)d_in[1];
    const float* bqkv = (const float*)d_in[2];
    const float* wd   = (const float*)d_in[3];
    const float* bd   = (const float*)d_in[4];
    float* out = (float*)d_out;

    float *qkv = nullptr, *attn = nullptr;
    cudaGetSymbolAddress((void**)&qkv,  g_qkv);
    cudaGetSymbolAddress((void**)&attn, g_attn);

    cudaFuncSetAttribute(gemm_tf32_mma,
                         cudaFuncAttributeMaxDynamicSharedMemorySize, GT_SMEM);
    cudaFuncSetAttribute(attn_mma_kernel,
                         cudaFuncAttributeMaxDynamicSharedMemorySize, AT_SMEM_B);

    // 1) qkv = hs @ w_qkv^T + b_qkv      [8192, 6144]
    {
        dim3 grid(NQKV / 128, M_ROWS / 128);
        gemm_tf32_mma<<<grid, 256, GT_SMEM>>>(hs, wqkv, bqkv, qkv, NQKV, HID);
    }
    // 2) causal flash attention          [8192, 2048]
    {
        dim3 grid(SEQ / 128, BATCH * NHEADS);
        attn_mma_kernel<<<grid, 256, AT_SMEM_B>>>(qkv, attn);
    }
    // 3) out = attn @ w_dense^T + b_dense [8192, 2048]
    {
        dim3 grid(HID / 128, M_ROWS / 128);
        gemm_tf32_mma<<<grid, 256, GT_SMEM>>>(attn, wd, bd, out, HID, HID);
    }
}

// round 8
// speedup vs baseline: 3.3950x; 1.0853x over previous
#include <cuda_runtime.h>
#include <cuda_bf16.h>
#include <cstdint>

// Problem constants
#define M_ROWS   8192          // B*S
#define HID      2048
#define NQKV     6144
#define NHEADS   16
#define HEADD    128
#define BATCH    4
#define SEQ      2048

// Scratch (device globals: allocation-free rule)
__device__ float g_qkv[M_ROWS * NQKV];     // [8192, 6144] fp32
__device__ float g_attn[M_ROWS * HID];     // [8192, 2048] tf32-rounded bits
__device__ float g_hst[M_ROWS * HID];      // hs pre-rounded to tf32
__device__ float g_wqt[NQKV * HID];        // w_qkv pre-rounded
__device__ float g_wdt[HID * HID];         // w_dense pre-rounded

// ---------------------------------------------------------------------------
// tf32 helpers (portable PTX, sm_80+; no tcgen05 — harness targets sm_103)
// ---------------------------------------------------------------------------
__device__ __forceinline__ uint32_t cvt_tf32(float f) {
    uint32_t r;
    asm("cvt.rna.tf32.f32 %0, %1;" : "=r"(r) : "f"(f));
    return r;
}

__device__ __forceinline__ void mma_tf32(float& d0, float& d1, float& d2, float& d3,
                                         uint32_t a0, uint32_t a1, uint32_t a2, uint32_t a3,
                                         uint32_t b0, uint32_t b1) {
    asm volatile(
        "mma.sync.aligned.m16n8k8.row.col.f32.tf32.tf32.f32 "
        "{%0,%1,%2,%3}, {%4,%5,%6,%7}, {%8,%9}, {%0,%1,%2,%3};"
        : "+f"(d0), "+f"(d1), "+f"(d2), "+f"(d3)
        : "r"(a0), "r"(a1), "r"(a2), "r"(a3), "r"(b0), "r"(b1));
}

#define CP_ASYNC16(dst, src) \
    asm volatile("cp.async.cg.shared.global [%0], [%1], 16;" \
                 :: "r"(dst), "l"(src))
#define CP_COMMIT() asm volatile("cp.async.commit_group;" ::: "memory")
#define CP_WAIT2()  asm volatile("cp.async.wait_group 2;"  ::: "memory")

__device__ __forceinline__ uint32_t smem_u32(const void* p) {
    uint32_t a;
    asm("{ .reg .u64 t; cvta.to.shared.u64 t, %1; cvt.u32.u64 %0, t; }"
        : "=r"(a) : "l"(p));
    return a;
}

// ---------------------------------------------------------------------------
// Pre-round fp32 -> tf32 bits (elementwise, float4)
// ---------------------------------------------------------------------------
__global__ void round_tf32_knl(const float4* __restrict__ s,
                               float4* __restrict__ d, int n4)
{
    int i = blockIdx.x * blockDim.x + threadIdx.x;
    if (i < n4) {
        float4 f = s[i];
        uint4 u = make_uint4(cvt_tf32(f.x), cvt_tf32(f.y),
                             cvt_tf32(f.z), cvt_tf32(f.w));
        *(uint4*)(d + i) = u;
    }
}

// ---------------------------------------------------------------------------
// tf32 tensor-core GEMM v2: C[M,N] = A[M,K] @ Bt[N,K]^T + bias[N]
// A, Bt hold PRE-ROUNDED tf32 bits. CTA tile 256x128, 8 warps (4 M x 2 N),
// warp tile 64x64 (16 FLOP/smem-byte -> tensor-bound). BK=32.
// cp.async 3-stage pipeline, no register staging, no cvt in hot loop.
// M mult of 256; N mult of 128; K mult of 32.
// ---------------------------------------------------------------------------
#define G2_PITCH   36
#define G2_STAGE_F (384 * G2_PITCH)            // A(256 rows)+B(128 rows)
#define G2_SMEM    (3 * G2_STAGE_F * 4)        // 165888 bytes

__global__ __launch_bounds__(256, 1)
void gemm_tf32_v2(const float* __restrict__ A,
                  const float* __restrict__ Bt,
                  const float* __restrict__ bias,
                  float* __restrict__ C,
                  int N, int K)
{
    extern __shared__ __align__(16) uint32_t smu[];
    const uint32_t smb = smem_u32(smu);

    const int tid  = threadIdx.x;
    const int lane = tid & 31;
    const int wid  = tid >> 5;
    const int gid  = lane >> 2;
    const int tig  = lane & 3;
    const int wm   = (wid & 3) * 64;    // warp M offset (4 groups)
    const int wn   = (wid >> 2) * 64;   // warp N offset (2 groups)
    const int m0 = blockIdx.y * 256;
    const int n0 = blockIdx.x * 128;

    // staging geometry: 384 rows x 8 quads, 12 cp.async per thread
    const int srow = tid >> 3;          // base row (rows srow + 32j)
    const int sq4  = (tid & 7) * 4;     // quad offset (floats)

    float acc[4][8][4];
#pragma unroll
    for (int mt = 0; mt < 4; mt++)
#pragma unroll
        for (int nt = 0; nt < 8; nt++)
#pragma unroll
            for (int c = 0; c < 4; c++) acc[mt][nt][c] = 0.f;

    const int niter = K >> 5;

    // -- stage issuer --
    auto issue = [&](int kt, int slot) {
        const int k0 = kt << 5;
        const uint32_t sb = smb + (uint32_t)slot * (G2_STAGE_F * 4);
#pragma unroll
        for (int j = 0; j < 8; j++) {      // A rows 0..255
            int row = srow + 32 * j;
            uint32_t dst = sb + (uint32_t)(row * G2_PITCH + sq4) * 4;
            const float* src = A + (size_t)(m0 + row) * K + k0 + sq4;
            CP_ASYNC16(dst, src);
        }
#pragma unroll
        for (int j = 8; j < 12; j++) {     // B rows 256..383
            int row = srow + 32 * j;
            uint32_t dst = sb + (uint32_t)(row * G2_PITCH + sq4) * 4;
            const float* src = Bt + (size_t)(n0 + row - 256) * K + k0 + sq4;
            CP_ASYNC16(dst, src);
        }
    };

    issue(0, 0); CP_COMMIT();
    if (niter > 1) issue(1, 1);
    CP_COMMIT();

    for (int kt = 0; kt < niter; kt++) {
        if (kt + 2 < niter) issue(kt + 2, (kt + 2) % 3);
        CP_COMMIT();
        CP_WAIT2();
        __syncthreads();

        const uint32_t* As = smu + (kt % 3) * G2_STAGE_F;
        const uint32_t* Bs = As + 256 * G2_PITCH;

#pragma unroll
        for (int s = 0; s < 4; s++) {
            uint32_t af[4][4], bf[8][2];
#pragma unroll
            for (int mt = 0; mt < 4; mt++) {
                const uint32_t* p = As + (wm + mt * 16 + gid) * G2_PITCH + s * 8 + tig;
                af[mt][0] = p[0];
                af[mt][1] = p[8 * G2_PITCH];
                af[mt][2] = p[4];
                af[mt][3] = p[8 * G2_PITCH + 4];
            }
#pragma unroll
            for (int nt = 0; nt < 8; nt++) {
                const uint32_t* p = Bs + (wn + nt * 8 + gid) * G2_PITCH + s * 8 + tig;
                bf[nt][0] = p[0];
                bf[nt][1] = p[4];
            }
#pragma unroll
            for (int mt = 0; mt < 4; mt++)
#pragma unroll
                for (int nt = 0; nt < 8; nt++)
                    mma_tf32(acc[mt][nt][0], acc[mt][nt][1],
                             acc[mt][nt][2], acc[mt][nt][3],
                             af[mt][0], af[mt][1], af[mt][2], af[mt][3],
                             bf[nt][0], bf[nt][1]);
        }
        __syncthreads();    // protect slot before it is re-filled
    }

    // epilogue: +bias, store fp32
#pragma unroll
    for (int mt = 0; mt < 4; mt++) {
        const int r0 = m0 + wm + mt * 16 + gid;
#pragma unroll
        for (int nt = 0; nt < 8; nt++) {
            const int col = n0 + wn + nt * 8 + 2 * tig;
            float2 bb = *(const float2*)(bias + col);
            float2 o0, o1;
            o0.x = acc[mt][nt][0] + bb.x;
            o0.y = acc[mt][nt][1] + bb.y;
            o1.x = acc[mt][nt][2] + bb.x;
            o1.y = acc[mt][nt][3] + bb.y;
            *(float2*)(C + (size_t)r0 * N + col)       = o0;
            *(float2*)(C + (size_t)(r0 + 8) * N + col) = o1;
        }
    }
}

// ---------------------------------------------------------------------------
// Tensor-core flash attention (tf32 mma, causal) — R7 passing version;
// only change: epilogue stores tf32-rounded bits (feeds dense GEMM directly).
// ---------------------------------------------------------------------------
#define AT_QP 132
#define AT_KP 132
#define AT_VP 68
#define AT_PP 68
#define AT_SMEM_F (128*AT_QP + 64*AT_KP + 128*AT_VP + 128*AT_PP)
#define AT_SMEM_B (AT_SMEM_F * 4)     // 171008 bytes

__global__ __launch_bounds__(256, 1)
void attn_mma_kernel(const float* __restrict__ qkv, float* __restrict__ out)
{
    const int qt = blockIdx.x;
    const int bh = blockIdx.y;
    const int b  = bh >> 4;
    const int h  = bh & 15;
    const int q0 = qt * 128;

    const int tid  = threadIdx.x;
    const int lane = tid & 31;
    const int warp = tid >> 5;
    const int gid  = lane >> 2;
    const int tig  = lane & 3;
    const int wm   = warp * 16;

    extern __shared__ __align__(16) uint32_t asm_[];
    uint32_t* Qs = asm_;
    uint32_t* Ks = Qs + 128 * AT_QP;
    uint32_t* Vt = Ks + 64 * AT_KP;
    uint32_t* Ps = Vt + 128 * AT_VP;

    const float scale = 0.088388347648318447f;
    const float* base = qkv + (size_t)(b * SEQ) * NQKV + h * HEADD;

    {
        int r  = tid >> 1;
        int c0 = (tid & 1) * 64;
        const float* qp = base + (size_t)(q0 + r) * NQKV + c0;
        uint32_t* dst = Qs + r * AT_QP + c0;
#pragma unroll
        for (int j = 0; j < 16; j++) {
            float4 f = *(const float4*)(qp + j * 4);
            dst[j*4+0] = cvt_tf32(f.x * scale);
            dst[j*4+1] = cvt_tf32(f.y * scale);
            dst[j*4+2] = cvt_tf32(f.z * scale);
            dst[j*4+3] = cvt_tf32(f.w * scale);
        }
    }

    float O[16][4];
#pragma unroll
    for (int nt = 0; nt < 16; nt++)
#pragma unroll
        for (int c = 0; c < 4; c++) O[nt][c] = 0.f;
    float m0r = -1e30f, m1r = -1e30f;
    float l0r = 0.f,    l1r = 0.f;

    const int rA = q0 + wm + gid;
    const int rB = rA + 8;
    const int niter = qt * 2 + 2;

    for (int kt = 0; kt < niter; kt++) {
        const int k0 = kt * 64;
        __syncthreads();
        {
            int r  = tid >> 2;
            int c0 = (tid & 3) * 32;
            const float* kp = base + 2048 + (size_t)(k0 + r) * NQKV + c0;
            const float* vp = base + 4096 + (size_t)(k0 + r) * NQKV + c0;
            uint32_t* kdst = Ks + r * AT_KP + c0;
#pragma unroll
            for (int j = 0; j < 8; j++) {
                float4 f = *(const float4*)(kp + j * 4);
                kdst[j*4+0] = cvt_tf32(f.x);
                kdst[j*4+1] = cvt_tf32(f.y);
                kdst[j*4+2] = cvt_tf32(f.z);
                kdst[j*4+3] = cvt_tf32(f.w);
                float4 g = *(const float4*)(vp + j * 4);
                Vt[(c0 + j*4 + 0) * AT_VP + r] = cvt_tf32(g.x);
                Vt[(c0 + j*4 + 1) * AT_VP + r] = cvt_tf32(g.y);
                Vt[(c0 + j*4 + 2) * AT_VP + r] = cvt_tf32(g.z);
                Vt[(c0 + j*4 + 3) * AT_VP + r] = cvt_tf32(g.w);
            }
        }
        __syncthreads();

        float acc[8][4];
#pragma unroll
        for (int nt = 0; nt < 8; nt++)
#pragma unroll
            for (int c = 0; c < 4; c++) acc[nt][c] = 0.f;

#pragma unroll
        for (int s = 0; s < 16; s++) {
            const uint32_t* pa = Qs + (wm + gid) * AT_QP + s * 8 + tig;
            uint32_t a0 = pa[0];
            uint32_t a1 = pa[8 * AT_QP];
            uint32_t a2 = pa[4];
            uint32_t a3 = pa[8 * AT_QP + 4];
#pragma unroll
            for (int nt = 0; nt < 8; nt++) {
                const uint32_t* pb = Ks + (nt * 8 + gid) * AT_KP + s * 8 + tig;
                mma_tf32(acc[nt][0], acc[nt][1], acc[nt][2], acc[nt][3],
                         a0, a1, a2, a3, pb[0], pb[4]);
            }
        }

        if (kt >= niter - 2) {
#pragma unroll
            for (int nt = 0; nt < 8; nt++) {
                int c0c = k0 + nt * 8 + 2 * tig;
                if (c0c > rA)     acc[nt][0] = -1e30f;
                if (c0c + 1 > rA) acc[nt][1] = -1e30f;
                if (c0c > rB)     acc[nt][2] = -1e30f;
                if (c0c + 1 > rB) acc[nt][3] = -1e30f;
            }
        }

        float mx0 = -1e30f, mx1 = -1e30f;
#pragma unroll
        for (int nt = 0; nt < 8; nt++) {
            mx0 = fmaxf(mx0, fmaxf(acc[nt][0], acc[nt][1]));
            mx1 = fmaxf(mx1, fmaxf(acc[nt][2], acc[nt][3]));
        }
        mx0 = fmaxf(mx0, __shfl_xor_sync(0xffffffffu, mx0, 1));
        mx0 = fmaxf(mx0, __shfl_xor_sync(0xffffffffu, mx0, 2));
        mx1 = fmaxf(mx1, __shfl_xor_sync(0xffffffffu, mx1, 1));
        mx1 = fmaxf(mx1, __shfl_xor_sync(0xffffffffu, mx1, 2));

        float mn0 = fmaxf(m0r, mx0);
        float mn1 = fmaxf(m1r, mx1);
        float al0 = __expf(m0r - mn0);
        float al1 = __expf(m1r - mn1);

        float s0 = 0.f, s1 = 0.f;
        uint32_t* prowA = Ps + (wm + gid) * AT_PP + 2 * tig;
        uint32_t* prowB = prowA + 8 * AT_PP;
#pragma unroll
        for (int nt = 0; nt < 8; nt++) {
            float p00 = __expf(acc[nt][0] - mn0);
            float p01 = __expf(acc[nt][1] - mn0);
            float p10 = __expf(acc[nt][2] - mn1);
            float p11 = __expf(acc[nt][3] - mn1);
            s0 += p00 + p01;
            s1 += p10 + p11;
            uint2 wa = make_uint2(cvt_tf32(p00), cvt_tf32(p01));
            uint2 wb = make_uint2(cvt_tf32(p10), cvt_tf32(p11));
            *(uint2*)(prowA + nt * 8) = wa;
            *(uint2*)(prowB + nt * 8) = wb;
        }
        s0 += __shfl_xor_sync(0xffffffffu, s0, 1);
        s0 += __shfl_xor_sync(0xffffffffu, s0, 2);
        s1 += __shfl_xor_sync(0xffffffffu, s1, 1);
        s1 += __shfl_xor_sync(0xffffffffu, s1, 2);

        l0r = l0r * al0 + s0;  m0r = mn0;
        l1r = l1r * al1 + s1;  m1r = mn1;

#pragma unroll
        for (int nt = 0; nt < 16; nt++) {
            O[nt][0] *= al0;  O[nt][1] *= al0;
            O[nt][2] *= al1;  O[nt][3] *= al1;
        }
        __syncwarp();

#pragma unroll
        for (int s = 0; s < 8; s++) {
            const uint32_t* pa = Ps + (wm + gid) * AT_PP + s * 8 + tig;
            uint32_t a0 = pa[0];
            uint32_t a1 = pa[8 * AT_PP];
            uint32_t a2 = pa[4];
            uint32_t a3 = pa[8 * AT_PP + 4];
#pragma unroll
            for (int nt = 0; nt < 16; nt++) {
                const uint32_t* pb = Vt + (nt * 8 + gid) * AT_VP + s * 8 + tig;
                mma_tf32(O[nt][0], O[nt][1], O[nt][2], O[nt][3],
                         a0, a1, a2, a3, pb[0], pb[4]);
            }
        }
    }

    // epilogue: normalize + ROUND TO TF32 (dense GEMM consumes these bits raw)
    const float inv0 = 1.0f / l0r;
    const float inv1 = 1.0f / l1r;
    uint32_t* outA = (uint32_t*)(out + (size_t)(b * SEQ + rA) * HID + h * HEADD + 2 * tig);
    uint32_t* outB = (uint32_t*)(out + (size_t)(b * SEQ + rB) * HID + h * HEADD + 2 * tig);
#pragma unroll
    for (int nt = 0; nt < 16; nt++) {
        uint2 oa, ob;
        oa.x = cvt_tf32(O[nt][0] * inv0);  oa.y = cvt_tf32(O[nt][1] * inv0);
        ob.x = cvt_tf32(O[nt][2] * inv1);  ob.y = cvt_tf32(O[nt][3] * inv1);
        *(uint2*)(outA + nt * 8) = oa;
        *(uint2*)(outB + nt * 8) = ob;
    }
}

// ---------------------------------------------------------------------------
// Launch: pre-round -> QKV GEMM -> flash attention -> dense GEMM
// ---------------------------------------------------------------------------
extern "C" void kernel_launch(void* const* d_in, const int* in_sizes, int n_in,
                              void* d_out, int out_size)
{
    (void)in_sizes; (void)n_in; (void)out_size;
    const float* hs   = (const float*)d_in[0];
    const float* wqkv = (const float*)d_in[1];
    const float* bqkv = (const float*)d_in[2];
    const float* wd   = (const float*)d_in[3];
    const float* bd   = (const float*)d_in[4];
    float* out = (float*)d_out;

    float *qkv, *attn, *hst, *wqt, *wdt;
    cudaGetSymbolAddress((void**)&qkv,  g_qkv);
    cudaGetSymbolAddress((void**)&attn, g_attn);
    cudaGetSymbolAddress((void**)&hst,  g_hst);
    cudaGetSymbolAddress((void**)&wqt,  g_wqt);
    cudaGetSymbolAddress((void**)&wdt,  g_wdt);

    cudaFuncSetAttribute(gemm_tf32_v2,
                         cudaFuncAttributeMaxDynamicSharedMemorySize, G2_SMEM);
    cudaFuncSetAttribute(attn_mma_kernel,
                         cudaFuncAttributeMaxDynamicSharedMemorySize, AT_SMEM_B);

    // 0) pre-round inputs to tf32 bits
    {
        int n4;
        n4 = (M_ROWS * HID) / 4;
        round_tf32_knl<<<(n4 + 255) / 256, 256>>>((const float4*)hs,   (float4*)hst, n4);
        n4 = (NQKV * HID) / 4;
        round_tf32_knl<<<(n4 + 255) / 256, 256>>>((const float4*)wqkv, (float4*)wqt, n4);
        n4 = (HID * HID) / 4;
        round_tf32_knl<<<(n4 + 255) / 256, 256>>>((const float4*)wd,   (float4*)wdt, n4);
    }
    // 1) qkv = hs @ w_qkv^T + b_qkv      [8192, 6144]
    {
        dim3 grid(NQKV / 128, M_ROWS / 256);
        gemm_tf32_v2<<<grid, 256, G2_SMEM>>>(hst, wqt, bqkv, qkv, NQKV, HID);
    }
    // 2) causal flash attention          [8192, 2048] (tf32-rounded output)
    {
        dim3 grid(SEQ / 128, BATCH * NHEADS);
        attn_mma_kernel<<<grid, 256, AT_SMEM_B>>>(qkv, attn);
    }
    // 3) out = attn @ w_dense^T + b_dense [8192, 2048]
    {
        dim3 grid(HID / 128, M_ROWS / 256);
        gemm_tf32_v2<<<grid, 256, G2_SMEM>>>(attn, wdt, bd, out, HID, HID);
    }
}

// round 9
// speedup vs baseline: 3.9077x; 1.1510x over previous
#include <cuda_runtime.h>
#include <cuda_bf16.h>
#include <cstdint>

// Problem constants
#define M_ROWS   8192          // B*S
#define HID      2048
#define NQKV     6144
#define NHEADS   16
#define HEADD    128
#define BATCH    4
#define SEQ      2048

// Scratch (device globals: allocation-free rule)
__device__ float g_qkv[M_ROWS * NQKV];     // [8192, 6144] tf32-rounded bits
__device__ float g_attn[M_ROWS * HID];     // [8192, 2048] tf32-rounded bits
__device__ float g_vt[BATCH * NHEADS * HEADD * SEQ];  // V transposed [bh][d][s]
__device__ float g_hst[M_ROWS * HID];      // hs pre-rounded to tf32
__device__ float g_wqt[NQKV * HID];        // w_qkv pre-rounded
__device__ float g_wdt[HID * HID];         // w_dense pre-rounded

// ---------------------------------------------------------------------------
// tf32 helpers (portable PTX, sm_80+; no tcgen05 — harness targets sm_103)
// ---------------------------------------------------------------------------
__device__ __forceinline__ uint32_t cvt_tf32(float f) {
    uint32_t r;
    asm("cvt.rna.tf32.f32 %0, %1;" : "=r"(r) : "f"(f));
    return r;
}

__device__ __forceinline__ void mma_tf32(float& d0, float& d1, float& d2, float& d3,
                                         uint32_t a0, uint32_t a1, uint32_t a2, uint32_t a3,
                                         uint32_t b0, uint32_t b1) {
    asm volatile(
        "mma.sync.aligned.m16n8k8.row.col.f32.tf32.tf32.f32 "
        "{%0,%1,%2,%3}, {%4,%5,%6,%7}, {%8,%9}, {%0,%1,%2,%3};"
        : "+f"(d0), "+f"(d1), "+f"(d2), "+f"(d3)
        : "r"(a0), "r"(a1), "r"(a2), "r"(a3), "r"(b0), "r"(b1));
}

#define CP_ASYNC16(dst, src) \
    asm volatile("cp.async.cg.shared.global [%0], [%1], 16;" \
                 :: "r"(dst), "l"(src))
#define CP_COMMIT()  asm volatile("cp.async.commit_group;" ::: "memory")
#define CP_WAIT(n)   asm volatile("cp.async.wait_group %0;" :: "n"(n) : "memory")

__device__ __forceinline__ uint32_t smem_u32(const void* p) {
    uint32_t a;
    asm("{ .reg .u64 t; cvta.to.shared.u64 t, %1; cvt.u32.u64 %0, t; }"
        : "=r"(a) : "l"(p));
    return a;
}

// ---------------------------------------------------------------------------
// Pre-round fp32 -> tf32 bits (elementwise, float4)
// ---------------------------------------------------------------------------
__global__ void round_tf32_knl(const float4* __restrict__ s,
                               float4* __restrict__ d, int n4)
{
    int i = blockIdx.x * blockDim.x + threadIdx.x;
    if (i < n4) {
        float4 f = s[i];
        uint4 u = make_uint4(cvt_tf32(f.x), cvt_tf32(f.y),
                             cvt_tf32(f.z), cvt_tf32(f.w));
        *(uint4*)(d + i) = u;
    }
}

// ---------------------------------------------------------------------------
// Transpose V section of qkv into g_vt[bh][d][s]  (V already tf32-rounded)
// ---------------------------------------------------------------------------
__global__ void transpose_v_knl(const float* __restrict__ qkv,
                                float* __restrict__ vt)
{
    __shared__ float t[32][33];
    const int bh = blockIdx.z;
    const int b  = bh >> 4;
    const int h  = bh & 15;
    const int s0 = blockIdx.x * 32;
    const int d0 = blockIdx.y * 32;
    const int tx = threadIdx.x, ty = threadIdx.y;   // 32 x 8

    const float* src = qkv + (size_t)(b * SEQ + s0) * NQKV + 4096 + h * HEADD + d0;
#pragma unroll
    for (int j = 0; j < 4; j++)
        t[ty + 8 * j][tx] = src[(size_t)(ty + 8 * j) * NQKV + tx];
    __syncthreads();
    float* dst = vt + ((size_t)bh * HEADD + d0) * SEQ + s0;
#pragma unroll
    for (int j = 0; j < 4; j++)
        dst[(size_t)(ty + 8 * j) * SEQ + tx] = t[tx][ty + 8 * j];
}

// ---------------------------------------------------------------------------
// tf32 tensor-core GEMM v3: C[M,N] = A[M,K] @ Bt[N,K]^T + bias[N]
// A, Bt hold PRE-ROUNDED tf32 bits. CTA 256x128, 8 warps (4M x 2N),
// warp tile 64x64. BK=32. 4-stage cp.async pipeline, ONE barrier per iter.
// round_out: store tf32-rounded bits (1) or plain fp32 (0).
// ---------------------------------------------------------------------------
#define G3_PITCH   36
#define G3_STAGE_F (384 * G3_PITCH)            // A(256 rows)+B(128 rows)
#define G3_SMEM    (4 * G3_STAGE_F * 4)        // 221184 bytes

__global__ __launch_bounds__(256, 1)
void gemm_tf32_v3(const float* __restrict__ A,
                  const float* __restrict__ Bt,
                  const float* __restrict__ bias,
                  float* __restrict__ C,
                  int N, int K, int round_out)
{
    extern __shared__ __align__(16) uint32_t smu[];
    const uint32_t smb = smem_u32(smu);

    const int tid  = threadIdx.x;
    const int lane = tid & 31;
    const int wid  = tid >> 5;
    const int gid  = lane >> 2;
    const int tig  = lane & 3;
    const int wm   = (wid & 3) * 64;
    const int wn   = (wid >> 2) * 64;
    const int m0 = blockIdx.y * 256;
    const int n0 = blockIdx.x * 128;

    const int srow = tid >> 3;
    const int sq4  = (tid & 7) * 4;

    float acc[4][8][4];
#pragma unroll
    for (int mt = 0; mt < 4; mt++)
#pragma unroll
        for (int nt = 0; nt < 8; nt++)
#pragma unroll
            for (int c = 0; c < 4; c++) acc[mt][nt][c] = 0.f;

    const int niter = K >> 5;

    auto issue = [&](int kt, int slot) {
        const int k0 = kt << 5;
        const uint32_t sb = smb + (uint32_t)slot * (G3_STAGE_F * 4);
#pragma unroll
        for (int j = 0; j < 8; j++) {      // A rows 0..255
            int row = srow + 32 * j;
            uint32_t dst = sb + (uint32_t)(row * G3_PITCH + sq4) * 4;
            const float* src = A + (size_t)(m0 + row) * K + k0 + sq4;
            CP_ASYNC16(dst, src);
        }
#pragma unroll
        for (int j = 8; j < 12; j++) {     // B rows 256..383
            int row = srow + 32 * j;
            uint32_t dst = sb + (uint32_t)(row * G3_PITCH + sq4) * 4;
            const float* src = Bt + (size_t)(n0 + row - 256) * K + k0 + sq4;
            CP_ASYNC16(dst, src);
        }
    };

    issue(0, 0); CP_COMMIT();
    issue(1, 1); CP_COMMIT();
    issue(2, 2); CP_COMMIT();

    for (int kt = 0; kt < niter; kt++) {
        CP_WAIT(2);              // stage kt resident (2 newer groups may pend)
        __syncthreads();         // publish to all warps; also closes iter kt-1

        const uint32_t* As = smu + (kt & 3) * G3_STAGE_F;
        const uint32_t* Bs = As + 256 * G3_PITCH;

#pragma unroll
        for (int s = 0; s < 4; s++) {
            uint32_t af[4][4], bf[8][2];
#pragma unroll
            for (int mt = 0; mt < 4; mt++) {
                const uint32_t* p = As + (wm + mt * 16 + gid) * G3_PITCH + s * 8 + tig;
                af[mt][0] = p[0];
                af[mt][1] = p[8 * G3_PITCH];
                af[mt][2] = p[4];
                af[mt][3] = p[8 * G3_PITCH + 4];
            }
#pragma unroll
            for (int nt = 0; nt < 8; nt++) {
                const uint32_t* p = Bs + (wn + nt * 8 + gid) * G3_PITCH + s * 8 + tig;
                bf[nt][0] = p[0];
                bf[nt][1] = p[4];
            }
#pragma unroll
            for (int mt = 0; mt < 4; mt++)
#pragma unroll
                for (int nt = 0; nt < 8; nt++)
                    mma_tf32(acc[mt][nt][0], acc[mt][nt][1],
                             acc[mt][nt][2], acc[mt][nt][3],
                             af[mt][0], af[mt][1], af[mt][2], af[mt][3],
                             bf[nt][0], bf[nt][1]);
        }

        // refill the slot consumed at iter kt-1 (all warps passed this iter's
        // barrier, which is after their kt-1 compute)
        if (kt + 3 < niter) issue(kt + 3, (kt + 3) & 3);
        CP_COMMIT();             // always commit: keeps group indexing uniform
    }

    // epilogue
#pragma unroll
    for (int mt = 0; mt < 4; mt++) {
        const int r0 = m0 + wm + mt * 16 + gid;
#pragma unroll
        for (int nt = 0; nt < 8; nt++) {
            const int col = n0 + wn + nt * 8 + 2 * tig;
            float2 bb = *(const float2*)(bias + col);
            float v00 = acc[mt][nt][0] + bb.x;
            float v01 = acc[mt][nt][1] + bb.y;
            float v10 = acc[mt][nt][2] + bb.x;
            float v11 = acc[mt][nt][3] + bb.y;
            if (round_out) {
                uint2 o0 = make_uint2(cvt_tf32(v00), cvt_tf32(v01));
                uint2 o1 = make_uint2(cvt_tf32(v10), cvt_tf32(v11));
                *(uint2*)(C + (size_t)r0 * N + col)       = o0;
                *(uint2*)(C + (size_t)(r0 + 8) * N + col) = o1;
            } else {
                *(float2*)(C + (size_t)r0 * N + col)       = make_float2(v00, v01);
                *(float2*)(C + (size_t)(r0 + 8) * N + col) = make_float2(v10, v11);
            }
        }
    }
}

// ---------------------------------------------------------------------------
// Tensor-core flash attention v2 (tf32 mma, causal).
// BQ=128, BK=64, D=128. 256 threads = 8 warps; warp w owns q-rows w*16..+15.
// Q fragments live in REGISTERS (loaded once). K and Vt (pre-transposed in
// gmem) are double-buffered via cp.async: loads for kt+1 overlap compute kt.
// K/V/Q data is already tf32-rounded by the QKV GEMM.
// ---------------------------------------------------------------------------
#define AV_KP 132                  // K buffer pitch (row = 128 + 4 pad)
#define AV_VP 68                   // Vt buffer pitch (row = 64 + 4 pad)
#define AV_BUF_F (64 * AV_KP + 128 * AV_VP)     // 17152 floats per stage
#define AV_PS_F  (128 * 68)                     // 8704 floats
#define AV_SMEM_F (2 * AV_BUF_F + AV_PS_F)      // 43008 floats
#define AV_SMEM_B (AV_SMEM_F * 4)               // 172032 bytes
#define AV_QP 132                  // Q staging pitch (temporary, inside bufs)

__global__ __launch_bounds__(256, 1)
void attn_mma_v2(const float* __restrict__ qkv,
                 const float* __restrict__ vt,
                 float* __restrict__ out)
{
    const int qt = blockIdx.x;       // 0..15
    const int bh = blockIdx.y;       // 0..63
    const int b  = bh >> 4;
    const int h  = bh & 15;
    const int q0 = qt * 128;

    const int tid  = threadIdx.x;
    const int lane = tid & 31;
    const int warp = tid >> 5;
    const int gid  = lane >> 2;
    const int tig  = lane & 3;
    const int wm   = warp * 16;

    extern __shared__ __align__(16) uint32_t asv[];
    const uint32_t smb = smem_u32(asv);
    // buffers: [buf0: K(64x132) Vt(128x68)][buf1: same], then Ps
    uint32_t* Ps = asv + 2 * AV_BUF_F;

    const float scale = 0.088388347648318447f;
    const float* base  = qkv + (size_t)(b * SEQ) * NQKV + h * HEADD;
    const float* vbase = vt + (size_t)bh * HEADD * SEQ;

    // ---- stage Q into (temporary) smem, then lift fragments to registers ----
    {
        int r  = tid >> 1;
        int c0 = (tid & 1) * 64;
        const float* qp = base + (size_t)(q0 + r) * NQKV + c0;
        uint32_t* dst = asv + r * AV_QP + c0;
#pragma unroll
        for (int j = 0; j < 16; j++) {
            float4 f = *(const float4*)(qp + j * 4);
            dst[j*4+0] = cvt_tf32(f.x * scale);
            dst[j*4+1] = cvt_tf32(f.y * scale);
            dst[j*4+2] = cvt_tf32(f.z * scale);
            dst[j*4+3] = cvt_tf32(f.w * scale);
        }
    }
    __syncthreads();

    uint32_t qf[16][4];
#pragma unroll
    for (int s = 0; s < 16; s++) {
        const uint32_t* pa = asv + (wm + gid) * AV_QP + s * 8 + tig;
        qf[s][0] = pa[0];
        qf[s][1] = pa[8 * AV_QP];
        qf[s][2] = pa[4];
        qf[s][3] = pa[8 * AV_QP + 4];
    }
    __syncthreads();     // everyone done reading Q staging; buffers reusable

    const int niter = qt * 2 + 2;

    // ---- KV stage issuer: K tile [64][128], Vt tile [128][64] ----
    auto issue_kv = [&](int kt, int slot) {
        const int k0 = kt * 64;
        const uint32_t sb = smb + (uint32_t)slot * (AV_BUF_F * 4);
        // K: 64 rows x 32 quads; thread -> row tid>>2, quads (tid&3)*8 + j
        {
            int r = tid >> 2;
            const float* src0 = base + 2048 + (size_t)(k0 + r) * NQKV;
            uint32_t d0 = sb + (uint32_t)(r * AV_KP) * 4;
#pragma unroll
            for (int j = 0; j < 8; j++) {
                int col = ((tid & 3) * 8 + j) * 4;
                CP_ASYNC16(d0 + col * 4, src0 + col);
            }
        }
        // Vt: 128 rows (d) x 16 quads; thread -> d tid>>1, quads (tid&1)*8 + j
        {
            int d = tid >> 1;
            const float* src0 = vbase + (size_t)d * SEQ + k0;
            uint32_t d0 = sb + (uint32_t)(64 * AV_KP + d * AV_VP) * 4;
#pragma unroll
            for (int j = 0; j < 8; j++) {
                int col = ((tid & 1) * 8 + j) * 4;
                CP_ASYNC16(d0 + col * 4, src0 + col);
            }
        }
    };

    issue_kv(0, 0); CP_COMMIT();
    if (niter > 1) issue_kv(1, 1);
    CP_COMMIT();

    float O[16][4];
#pragma unroll
    for (int nt = 0; nt < 16; nt++)
#pragma unroll
        for (int c = 0; c < 4; c++) O[nt][c] = 0.f;
    float m0r = -1e30f, m1r = -1e30f;
    float l0r = 0.f,    l1r = 0.f;

    const int rA = q0 + wm + gid;
    const int rB = rA + 8;

    for (int kt = 0; kt < niter; kt++) {
        const int k0 = kt * 64;
        CP_WAIT(1);              // stage kt resident (1 newer group may pend)
        __syncthreads();

        const uint32_t* Ks = asv + (kt & 1) * AV_BUF_F;
        const uint32_t* Vs = Ks + 64 * AV_KP;

        // ---- S = Q K^T ----
        float acc[8][4];
#pragma unroll
        for (int nt = 0; nt < 8; nt++)
#pragma unroll
            for (int c = 0; c < 4; c++) acc[nt][c] = 0.f;

#pragma unroll
        for (int s = 0; s < 16; s++) {
#pragma unroll
            for (int nt = 0; nt < 8; nt++) {
                const uint32_t* pb = Ks + (nt * 8 + gid) * AV_KP + s * 8 + tig;
                mma_tf32(acc[nt][0], acc[nt][1], acc[nt][2], acc[nt][3],
                         qf[s][0], qf[s][1], qf[s][2], qf[s][3],
                         pb[0], pb[4]);
            }
        }

        // ---- causal mask ----
        if (kt >= niter - 2) {
#pragma unroll
            for (int nt = 0; nt < 8; nt++) {
                int c0c = k0 + nt * 8 + 2 * tig;
                if (c0c > rA)     acc[nt][0] = -1e30f;
                if (c0c + 1 > rA) acc[nt][1] = -1e30f;
                if (c0c > rB)     acc[nt][2] = -1e30f;
                if (c0c + 1 > rB) acc[nt][3] = -1e30f;
            }
        }

        // ---- online softmax (4-lane groups share a row) ----
        float mx0 = -1e30f, mx1 = -1e30f;
#pragma unroll
        for (int nt = 0; nt < 8; nt++) {
            mx0 = fmaxf(mx0, fmaxf(acc[nt][0], acc[nt][1]));
            mx1 = fmaxf(mx1, fmaxf(acc[nt][2], acc[nt][3]));
        }
        mx0 = fmaxf(mx0, __shfl_xor_sync(0xffffffffu, mx0, 1));
        mx0 = fmaxf(mx0, __shfl_xor_sync(0xffffffffu, mx0, 2));
        mx1 = fmaxf(mx1, __shfl_xor_sync(0xffffffffu, mx1, 1));
        mx1 = fmaxf(mx1, __shfl_xor_sync(0xffffffffu, mx1, 2));

        float mn0 = fmaxf(m0r, mx0);
        float mn1 = fmaxf(m1r, mx1);
        float al0 = __expf(m0r - mn0);
        float al1 = __expf(m1r - mn1);

        float s0 = 0.f, s1 = 0.f;
        uint32_t* prowA = Ps + (wm + gid) * 68 + 2 * tig;
        uint32_t* prowB = prowA + 8 * 68;
#pragma unroll
        for (int nt = 0; nt < 8; nt++) {
            float p00 = __expf(acc[nt][0] - mn0);
            float p01 = __expf(acc[nt][1] - mn0);
            float p10 = __expf(acc[nt][2] - mn1);
            float p11 = __expf(acc[nt][3] - mn1);
            s0 += p00 + p01;
            s1 += p10 + p11;
            *(uint2*)(prowA + nt * 8) = make_uint2(cvt_tf32(p00), cvt_tf32(p01));
            *(uint2*)(prowB + nt * 8) = make_uint2(cvt_tf32(p10), cvt_tf32(p11));
        }
        s0 += __shfl_xor_sync(0xffffffffu, s0, 1);
        s0 += __shfl_xor_sync(0xffffffffu, s0, 2);
        s1 += __shfl_xor_sync(0xffffffffu, s1, 1);
        s1 += __shfl_xor_sync(0xffffffffu, s1, 2);

        l0r = l0r * al0 + s0;  m0r = mn0;
        l1r = l1r * al1 + s1;  m1r = mn1;

#pragma unroll
        for (int nt = 0; nt < 16; nt++) {
            O[nt][0] *= al0;  O[nt][1] *= al0;
            O[nt][2] *= al1;  O[nt][3] *= al1;
        }
        __syncwarp();   // Ps rows are warp-private

        // ---- O += P V ----
#pragma unroll
        for (int s = 0; s < 8; s++) {
            const uint32_t* pa = Ps + (wm + gid) * 68 + s * 8 + tig;
            uint32_t a0 = pa[0];
            uint32_t a1 = pa[8 * 68];
            uint32_t a2 = pa[4];
            uint32_t a3 = pa[8 * 68 + 4];
#pragma unroll
            for (int nt = 0; nt < 16; nt++) {
                const uint32_t* pb = Vs + (nt * 8 + gid) * AV_VP + s * 8 + tig;
                mma_tf32(O[nt][0], O[nt][1], O[nt][2], O[nt][3],
                         a0, a1, a2, a3, pb[0], pb[4]);
            }
        }

        __syncthreads();   // all warps done reading buffer kt&1
        if (kt + 2 < niter) issue_kv(kt + 2, kt & 1);
        CP_COMMIT();       // always commit (uniform group indexing)
    }

    // ---- epilogue: normalize, round to tf32 (dense GEMM consumes raw) ----
    const float inv0 = 1.0f / l0r;
    const float inv1 = 1.0f / l1r;
    uint32_t* outA = (uint32_t*)(out + (size_t)(b * SEQ + rA) * HID + h * HEADD + 2 * tig);
    uint32_t* outB = (uint32_t*)(out + (size_t)(b * SEQ + rB) * HID + h * HEADD + 2 * tig);
#pragma unroll
    for (int nt = 0; nt < 16; nt++) {
        uint2 oa, ob;
        oa.x = cvt_tf32(O[nt][0] * inv0);  oa.y = cvt_tf32(O[nt][1] * inv0);
        ob.x = cvt_tf32(O[nt][2] * inv1);  ob.y = cvt_tf32(O[nt][3] * inv1);
        *(uint2*)(outA + nt * 8) = oa;
        *(uint2*)(outB + nt * 8) = ob;
    }
}

// ---------------------------------------------------------------------------
// Launch: pre-round -> QKV GEMM (tf32 out) -> V transpose -> attention -> dense
// ---------------------------------------------------------------------------
extern "C" void kernel_launch(void* const* d_in, const int* in_sizes, int n_in,
                              void* d_out, int out_size)
{
    (void)in_sizes; (void)n_in; (void)out_size;
    const float* hs   = (const float*)d_in[0];
    const float* wqkv = (const float*)d_in[1];
    const float* bqkv = (const float*)d_in[2];
    const float* wd   = (const float*)d_in[3];
    const float* bd   = (const float*)d_in[4];
    float* out = (float*)d_out;

    float *qkv, *attn, *vt, *hst, *wqt, *wdt;
    cudaGetSymbolAddress((void**)&qkv,  g_qkv);
    cudaGetSymbolAddress((void**)&attn, g_attn);
    cudaGetSymbolAddress((void**)&vt,   g_vt);
    cudaGetSymbolAddress((void**)&hst,  g_hst);
    cudaGetSymbolAddress((void**)&wqt,  g_wqt);
    cudaGetSymbolAddress((void**)&wdt,  g_wdt);

    cudaFuncSetAttribute(gemm_tf32_v3,
                         cudaFuncAttributeMaxDynamicSharedMemorySize, G3_SMEM);
    cudaFuncSetAttribute(attn_mma_v2,
                         cudaFuncAttributeMaxDynamicSharedMemorySize, AV_SMEM_B);

    // 0) pre-round inputs to tf32 bits
    {
        int n4;
        n4 = (M_ROWS * HID) / 4;
        round_tf32_knl<<<(n4 + 255) / 256, 256>>>((const float4*)hs,   (float4*)hst, n4);
        n4 = (NQKV * HID) / 4;
        round_tf32_knl<<<(n4 + 255) / 256, 256>>>((const float4*)wqkv, (float4*)wqt, n4);
        n4 = (HID * HID) / 4;
        round_tf32_knl<<<(n4 + 255) / 256, 256>>>((const float4*)wd,   (float4*)wdt, n4);
    }
    // 1) qkv = hs @ w_qkv^T + b_qkv      [8192, 6144], tf32-rounded output
    {
        dim3 grid(NQKV / 128, M_ROWS / 256);
        gemm_tf32_v3<<<grid, 256, G3_SMEM>>>(hst, wqt, bqkv, qkv, NQKV, HID, 1);
    }
    // 1b) transpose V into g_vt[bh][d][s]
    {
        dim3 grid(SEQ / 32, HEADD / 32, BATCH * NHEADS);
        transpose_v_knl<<<grid, dim3(32, 8)>>>(qkv, vt);
    }
    // 2) causal flash attention          [8192, 2048], tf32-rounded output
    {
        dim3 grid(SEQ / 128, BATCH * NHEADS);
        attn_mma_v2<<<grid, 256, AV_SMEM_B>>>(qkv, vt, attn);
    }
    // 3) out = attn @ w_dense^T + b_dense [8192, 2048], fp32 output
    {
        dim3 grid(HID / 128, M_ROWS / 256);
        gemm_tf32_v3<<<grid, 256, G3_SMEM>>>(attn, wdt, bd, out, HID, HID, 0);
    }
}